// round 17
// baseline (speedup 1.0000x reference)
#include <cuda_runtime.h>

// CfC recurrent kernel, round 17: K-partitioned GEMM2. 4-CTA clusters;
// CTA rank holds W0[:,64r:+64) (48KB) AND head-weight ROWS k in [64r,+64)
// for all 512 interleaved columns (128KB). GEMM2 consumes only the CTA's
// LOCAL f slice -> no f exchange, no barrier between GEMM1 and GEMM2.
// Per-thread GEMM2 partials are pushed directly to the gate-owner CTA;
// two adjacent cluster barriers bracket only the short gate phase.
// B=256, S=2048, C=64, U=128, H=256. 32 clusters x 4 CTAs x 256 threads.
// Packed fp32x2 FMA, row-pair lanes; 48/64 GEMM2 k-slices register-pinned.

typedef unsigned long long u64;

#define S_LEN 2048
#define NTHRD 256
#define KREG 48

// SMEM layout (u64 units)
#define OW0   0        // float[192][64]        6144 u64
#define OWH   6144     // float[64][512]        16384 u64 (k-major!)
#define OFEAT 22528    // u64 feat2[192][4]
#define OFSM  23296    // u64 fsm2[64][4]  (LOCAL f slice, rp lanes)
#define ORED  23552    // u64 red1[8][4][64]    2048 u64
#define OPIN  25600    // u64 pin[4][4][128]    2048 u64 (CTA, rp, col_local)
#define OTOT  27648
#define SMEM_BYTES (OTOT * 8)   // 221184

__device__ __forceinline__ u64 pack2(float lo, float hi) {
    u64 r;
    asm("mov.b64 %0, {%1, %2};"
        : "=l"(r) : "r"(__float_as_uint(lo)), "r"(__float_as_uint(hi)));
    return r;
}
__device__ __forceinline__ void fma2(u64& d, u64 a, u64 b) {
    asm("fma.rn.f32x2 %0, %1, %2, %0;" : "+l"(d) : "l"(a), "l"(b));
}
__device__ __forceinline__ u64 add2(u64 a, u64 b) {
    u64 r;
    asm("add.rn.f32x2 %0, %1, %2;" : "=l"(r) : "l"(a), "l"(b));
    return r;
}
__device__ __forceinline__ float2 unpk(u64 v) {
    unsigned lo, hi;
    asm("mov.b64 {%0, %1}, %2;" : "=r"(lo), "=r"(hi) : "l"(v));
    return make_float2(__uint_as_float(lo), __uint_as_float(hi));
}
__device__ __forceinline__ unsigned smem_u32(const void* p) {
    unsigned a;
    asm("{ .reg .u64 t; cvta.to.shared.u64 t, %1; cvt.u32.u64 %0, t; }"
        : "=r"(a) : "l"(p));
    return a;
}
__device__ __forceinline__ unsigned mapa_rank(unsigned addr, unsigned rank) {
    unsigned r;
    asm("mapa.shared::cluster.u32 %0, %1, %2;" : "=r"(r) : "r"(addr), "r"(rank));
    return r;
}
__device__ __forceinline__ void st_cluster(unsigned addr, u64 v) {
    asm volatile("st.shared::cluster.b64 [%0], %1;" :: "r"(addr), "l"(v) : "memory");
}
__device__ __forceinline__ unsigned ctarank() {
    unsigned r;
    asm("mov.u32 %0, %%cluster_ctarank;" : "=r"(r));
    return r;
}
#define CLUSTER_BAR() do { \
    asm volatile("barrier.cluster.arrive.aligned;" ::: "memory"); \
    asm volatile("barrier.cluster.wait.aligned;"   ::: "memory"); \
} while (0)

__global__ void __launch_bounds__(NTHRD, 1) __cluster_dims__(4, 1, 1)
cfc_kernel(
    const float* __restrict__ x_codes, const float* __restrict__ h0,
    const float* __restrict__ tsp,
    const float* __restrict__ W0, const float* __restrict__ b0,
    const float* __restrict__ W1, const float* __restrict__ b1,
    const float* __restrict__ W2, const float* __restrict__ b2,
    const float* __restrict__ Wa, const float* __restrict__ ba,
    const float* __restrict__ Wb, const float* __restrict__ bb,
    float* __restrict__ out)
{
    extern __shared__ u64 smu[];
    float* sW0 = (float*)(smu + OW0);
    float* sWH = (float*)(smu + OWH);     // [k_local 64][col 512], col=4j+h
    u64* feat2 = smu + OFEAT;
    u64* fsm2  = smu + OFSM;              // [k_local 64][rp 4]
    u64* red   = smu + ORED;
    u64* pin   = smu + OPIN;              // [src_cta 4][rp 4][col_local 128]

    const int tid = threadIdx.x;
    const unsigned rank = ctarank();
    const int brow = (blockIdx.x >> 2) * 8;

    // ---- one-time: W0 slice [192][64] (cols 64*rank..) ----
    for (int idx = tid; idx < 192 * 16; idx += NTHRD) {     // float4 units
        int k = idx >> 4, q = idx & 15;
        ((float4*)sW0)[idx] =
            *(const float4*)(W0 + (size_t)k * 256 + rank * 64 + q * 4);
    }
    // ---- head rows k in [64*rank, +64), all 512 interleaved cols ----
    // sWH[k][4j+h] = Wh[64*rank + k][j]
    for (int idx = tid; idx < 64 * 512; idx += NTHRD) {
        int k = idx >> 9, c = idx & 511, j = c >> 2, h = c & 3;
        const float* src = (h == 0 ? W1 : h == 1 ? W2 : h == 2 ? Wa : Wb);
        sWH[idx] = src[(size_t)(64 * (int)rank + k) * 128 + j];
    }
    // ---- h0 into feat2[64+u][rp] ----
    for (int idx = tid; idx < 512; idx += NTHRD) {
        int u = idx & 127, rp = idx >> 7;
        feat2[(64 + u) * 4 + rp] = pack2(h0[(size_t)(brow + 2 * rp) * 128 + u],
                                         h0[(size_t)(brow + 2 * rp + 1) * 128 + u]);
    }

    // ---- role constants ----
    // GEMM1: 32 col-groups (2 cols) x 8 kg (24 k), 4 rps each
    const int cg  = tid & 31;
    const int k1b = (tid >> 5) * 24;
    // reduce1: 64 cols x 4 rps (all 256 threads)
    const int col1 = tid & 63;
    const int rp1  = tid >> 6;
    const int gc1  = 64 * (int)rank + col1;
    const u64 b0d  = pack2(b0[gc1], b0[gc1]);
    // GEMM2: thread owns interleaved cols 2*tid, 2*tid+1 (same unit j=tid>>1)
    const int ownq = tid >> 6;               // gate-owner CTA of my unit
    const int cl   = 2 * (tid & 63);         // col_local within owner's 128
    // gate (tid<128): 32 units x 4 rps
    const int jg  = tid & 31;
    const int rpg = (tid >> 5) & 3;
    const int ug  = 32 * (int)rank + jg;
    const u64 b1d = pack2(b1[ug], b1[ug]);
    const u64 b2d = pack2(b2[ug], b2[ug]);
    const u64 bad = pack2(ba[ug], ba[ug]);
    const u64 bbd = pack2(bb[ug], bb[ug]);
    const int gr0 = brow + 2 * rpg;
    const float* tsa = tsp + (size_t)gr0 * S_LEN;
    const float* tsb = tsp + (size_t)(gr0 + 1) * S_LEN;
    float* outa = out + (size_t)gr0 * S_LEN * 128 + ug;
    float* outb = out + (size_t)(gr0 + 1) * S_LEN * 128 + ug;
    // x loader: 64 channels x 4 row-pairs (all 256 threads)
    const int ch  = tid & 63;
    const int rpx = tid >> 6;
    const float* xa = x_codes + (size_t)(brow + 2 * rpx) * S_LEN * 64 + ch;
    const float* xb = x_codes + (size_t)(brow + 2 * rpx + 1) * S_LEN * 64 + ch;

    __syncthreads();
    CLUSTER_BAR();   // weights + h0 visible cluster-wide

    // ---- remote base addresses ----
    unsigned pinb[4], featb[4];
    {
        unsigned lp = smem_u32(pin), lh = smem_u32(feat2);
        #pragma unroll
        for (int r = 0; r < 4; ++r) {
            pinb[r]  = mapa_rank(lp, (unsigned)r);
            featb[r] = mapa_rank(lh, (unsigned)r);
        }
    }
    const unsigned pushbase = pinb[ownq] + (unsigned)(((int)rank * 512 + cl) * 8);

    // ---- pin first KREG GEMM2 weight k-slices in registers ----
    float2 wreg[KREG];
    #pragma unroll
    for (int k = 0; k < KREG; ++k)
        wreg[k] = *(const float2*)(sWH + (size_t)k * 512 + 2 * tid);
    const float* wp2c = sWH + 2 * tid;

    float xr0 = xa[0], xr1 = xb[0];

    for (int s = 0; s < S_LEN; ++s) {
        float tsv0 = 0.f, tsv1 = 0.f;
        if (tid < 128) { tsv0 = tsa[s]; tsv1 = tsb[s]; }

        // write x(s) (scaled) into feat2[0..63]
        feat2[ch * 4 + rpx] = pack2((xr0 - 65.0f) * 0.01f, (xr1 - 65.0f) * 0.01f);
        __syncthreads();  // S1: feat (x + h) ready locally

        // ---- GEMM1 partials: 2 cols x 4 rps over 24 k ----
        u64 a00 = 0, a01 = 0, a02 = 0, a03 = 0;
        u64 a10 = 0, a11 = 0, a12 = 0, a13 = 0;
        {
            const float* wp = sW0 + k1b * 64 + 2 * cg;
            const u64* fp = feat2 + k1b * 4;
            #pragma unroll 12
            for (int k = 0; k < 24; ++k) {
                float2 w = *(const float2*)(wp + k * 64);
                u64 w0d = pack2(w.x, w.x), w1d = pack2(w.y, w.y);
                ulonglong2 f01 = *(const ulonglong2*)(fp + k * 4);
                ulonglong2 f23 = *(const ulonglong2*)(fp + k * 4 + 2);
                fma2(a00, f01.x, w0d); fma2(a01, f01.y, w0d);
                fma2(a02, f23.x, w0d); fma2(a03, f23.y, w0d);
                fma2(a10, f01.x, w1d); fma2(a11, f01.y, w1d);
                fma2(a12, f23.x, w1d); fma2(a13, f23.y, w1d);
            }
        }
        {
            u64* rb = red + (tid >> 5) * 256 + 2 * cg;   // [ks8][rp4][col64]
            *(ulonglong2*)(rb)       = make_ulonglong2(a00, a10);
            *(ulonglong2*)(rb + 64)  = make_ulonglong2(a01, a11);
            *(ulonglong2*)(rb + 128) = make_ulonglong2(a02, a12);
            *(ulonglong2*)(rb + 192) = make_ulonglong2(a03, a13);
        }
        __syncthreads();  // S2: red1 ready

        // ---- reduce1 + lecun_tanh -> LOCAL fsm2 (no exchange!) ----
        {
            const u64* rr = red + rp1 * 64 + col1;
            u64 ssum = rr[0];
            #pragma unroll
            for (int q = 1; q < 8; ++q) ssum = add2(ssum, rr[q * 256]);
            ssum = add2(ssum, b0d);
            float2 v = unpk(ssum);
            fsm2[col1 * 4 + rp1] = pack2(1.7159f * tanhf(0.666f * v.x),
                                         1.7159f * tanhf(0.666f * v.y));
        }
        __syncthreads();  // S2b: local f slice ready

        // ---- GEMM2: 2 cols x 4 rps over LOCAL 64 k (48 reg + 16 smem w) ----
        u64 q00 = 0, q01 = 0, q02 = 0, q03 = 0;
        u64 q10 = 0, q11 = 0, q12 = 0, q13 = 0;
        #pragma unroll
        for (int k = 0; k < KREG; ++k) {
            float2 w = wreg[k];
            u64 w0d = pack2(w.x, w.x), w1d = pack2(w.y, w.y);
            ulonglong2 f01 = *(const ulonglong2*)(fsm2 + k * 4);
            ulonglong2 f23 = *(const ulonglong2*)(fsm2 + k * 4 + 2);
            fma2(q00, f01.x, w0d); fma2(q01, f01.y, w0d);
            fma2(q02, f23.x, w0d); fma2(q03, f23.y, w0d);
            fma2(q10, f01.x, w1d); fma2(q11, f01.y, w1d);
            fma2(q12, f23.x, w1d); fma2(q13, f23.y, w1d);
        }
        #pragma unroll 8
        for (int k = KREG; k < 64; ++k) {
            float2 w = *(const float2*)(wp2c + (size_t)k * 512);
            u64 w0d = pack2(w.x, w.x), w1d = pack2(w.y, w.y);
            ulonglong2 f01 = *(const ulonglong2*)(fsm2 + k * 4);
            ulonglong2 f23 = *(const ulonglong2*)(fsm2 + k * 4 + 2);
            fma2(q00, f01.x, w0d); fma2(q01, f01.y, w0d);
            fma2(q02, f23.x, w0d); fma2(q03, f23.y, w0d);
            fma2(q10, f01.x, w1d); fma2(q11, f01.y, w1d);
            fma2(q12, f23.x, w1d); fma2(q13, f23.y, w1d);
        }
        // ---- push complete partial straight to gate-owner CTA ----
        // pin[src=rank][rp][col_local]: rp stride = 128 u64 = 1024 B
        st_cluster(pushbase + 0,        q00); st_cluster(pushbase + 8,        q10);
        st_cluster(pushbase + 1024,     q01); st_cluster(pushbase + 1024 + 8, q11);
        st_cluster(pushbase + 2048,     q02); st_cluster(pushbase + 2048 + 8, q12);
        st_cluster(pushbase + 3072,     q03); st_cluster(pushbase + 3072 + 8, q13);

        // prefetch x(s+1) while the exchange drains
        if (s + 1 < S_LEN) { xr0 = xa[(size_t)(s + 1) * 64]; xr1 = xb[(size_t)(s + 1) * 64]; }

        CLUSTER_BAR();  // BAR_A: all partials delivered to owners

        // ---- gate: reduce 4 CTA-partials, sigmoid blend, out + h-push ----
        if (tid < 128) {
            const u64* rr = pin + rpg * 128 + 4 * jg;
            ulonglong2 g0 = *(const ulonglong2*)(rr);       // (ff1,ff2) partial
            ulonglong2 g1 = *(const ulonglong2*)(rr + 2);   // (ta, tb ) partial
            u64 p1 = g0.x, p2 = g0.y, pa = g1.x, pb = g1.y;
            #pragma unroll
            for (int r = 1; r < 4; ++r) {
                ulonglong2 u0 = *(const ulonglong2*)(rr + r * 512);
                ulonglong2 u1 = *(const ulonglong2*)(rr + r * 512 + 2);
                p1 = add2(p1, u0.x); p2 = add2(p2, u0.y);
                pa = add2(pa, u1.x); pb = add2(pb, u1.y);
            }
            p1 = add2(p1, b1d); p2 = add2(p2, b2d);
            pa = add2(pa, bad); pb = add2(pb, bbd);
            float2 f1v = unpk(p1), f2v = unpk(p2), av = unpk(pa), bv = unpk(pb);
            float ti0 = 1.0f / (1.0f + expf(av.x * tsv0 - bv.x));
            float ti1 = 1.0f / (1.0f + expf(av.y * tsv1 - bv.y));
            float nh0 = f1v.x + ti0 * (f2v.x - f1v.x);
            float nh1 = f1v.y + ti1 * (f2v.y - f1v.y);
            outa[(size_t)s * 128] = nh0;
            outb[(size_t)s * 128] = nh1;
            u64 hv = pack2(nh0, nh1);
            unsigned off = (unsigned)(((64 + ug) * 4 + rpg) * 8);
            #pragma unroll
            for (int r = 0; r < 4; ++r) st_cluster(featb[r] + off, hv);
        }
        CLUSTER_BAR();  // BAR_B: h delivered everywhere; exit-safe on last step
    }
}

extern "C" void kernel_launch(void* const* d_in, const int* in_sizes, int n_in,
                              void* d_out, int out_size) {
    const float* x_codes = (const float*)d_in[0];
    const float* h0      = (const float*)d_in[1];
    const float* tsp     = (const float*)d_in[2];
    const float* W0      = (const float*)d_in[3];
    const float* b0      = (const float*)d_in[4];
    const float* W1      = (const float*)d_in[5];
    const float* b1      = (const float*)d_in[6];
    const float* W2      = (const float*)d_in[7];
    const float* b2      = (const float*)d_in[8];
    const float* Wa      = (const float*)d_in[9];
    const float* ba      = (const float*)d_in[10];
    const float* Wb      = (const float*)d_in[11];
    const float* bb      = (const float*)d_in[12];
    float* out = (float*)d_out;

    cudaFuncSetAttribute(cfc_kernel,
                         cudaFuncAttributeMaxDynamicSharedMemorySize, SMEM_BYTES);

    cfc_kernel<<<128, NTHRD, SMEM_BYTES>>>(
        x_codes, h0, tsp, W0, b0, W1, b1, W2, b2, Wa, ba, Wb, bb, out);
}